// round 15
// baseline (speedup 1.0000x reference)
#include <cuda_runtime.h>
#include <math_constants.h>
#include <cstdint>

// Tropical (max-plus) depthwise 5x5 conv, stride=1, pad=2, dil=1.
// x: (8,32,224,224) f32, kernel: (32,1,5,5) f32, out same shape as x.
// out[b,c,y,x] = max_{i,j} x[b,c, y+i-2, x+j-2] + kernel[c,0,4-i,4-j]
//
// R15: all smem-tile shapes plateau at 29-31us kernel (issue 58-80%, L1
// 70-81%). This version has NO shared memory: each thread owns a 4-col x
// 28-row strip and slides a 5-row ring of accumulators down 32 input rows,
// loading exactly the 8 needed floats per row (8B+16B+8B aligned LDG) and
// storing one finished output row per step. ~95% of the issue stream is
// FADD/FMNMX; no barriers, no LDS, weights via UR+const-bank operands.

static constexpr int Hdim = 224;
static constexpr int Wdim = 224;
static constexpr int NCG  = 56;    // 4-wide column groups per row

__constant__ float cw[32 * 25];    // raw (unflipped) kernel from d_in[1]

// flipped weight (i,j): kernel[c,0,4-i,4-j] = cw[base + 24 - (5i+j)]
#define WGT(i, j) cw[wbase + (24 - ((i) * 5 + (j)))]

// One sliding step. K = r mod 5 (compile-time), R = input-row index r
// (gy = ys - 2 + r). Finalizes/stores output row y = ys + r - 4 if DOSTORE.
#define STEP(K, R, ROWOK, DOSTORE)                                          \
  {                                                                         \
    const float* rp = bx + (R) * Wdim;                                      \
    float2 lp = ((ROWOK) && okL) ? *(const float2*)(rp - 2)                 \
                                 : make_float2(NI, NI);                     \
    float4 mp = (ROWOK) ? *(const float4*)(rp)                              \
                        : make_float4(NI, NI, NI, NI);                      \
    float2 hp = ((ROWOK) && okR) ? *(const float2*)(rp + 4)                 \
                                 : make_float2(NI, NI);                     \
    const float xw[8] = {lp.x, lp.y, mp.x, mp.y, mp.z, mp.w, hp.x, hp.y};   \
    _Pragma("unroll")                                                       \
    for (int i = 0; i < 5; i++) {                                           \
      const int s = ((K) - i + 5) % 5;                                      \
      _Pragma("unroll")                                                     \
      for (int t = 0; t < 4; t++) {                                         \
        float h = xw[t] + WGT(i, 0);                                        \
        h = fmaxf(h, xw[t + 1] + WGT(i, 1));                                \
        h = fmaxf(h, xw[t + 2] + WGT(i, 2));                                \
        h = fmaxf(h, xw[t + 3] + WGT(i, 3));                                \
        h = fmaxf(h, xw[t + 4] + WGT(i, 4));                                \
        if (i == 0) acc[s][t] = h;                                          \
        else        acc[s][t] = fmaxf(acc[s][t], h);                        \
      }                                                                     \
    }                                                                       \
    if (DOSTORE) {                                                          \
      const int ss = ((K) + 1) % 5;  /* == (K-4+5)%5 */                     \
      *(float4*)(bo + (R) * Wdim) =                                         \
          make_float4(acc[ss][0], acc[ss][1], acc[ss][2], acc[ss][3]);      \
    }                                                                       \
  }

__global__ __launch_bounds__(224, 4)
void tropical_conv_kernel(const float* __restrict__ x,
                          float* __restrict__ out) {
    const int cg    = threadIdx.x;                       // 0..55
    const int strip = blockIdx.y * 4 + threadIdx.y;      // 0..7
    const int bc    = blockIdx.z;                        // b*32 + c
    const int wbase = (bc & 31) * 25;                    // block-uniform -> UR
    const int ys    = strip * 28;
    const int x0    = 4 * cg;

    const float* __restrict__ bx =
        x + (size_t)bc * (Hdim * Wdim) + (ys - 2) * Wdim + x0;
    float* __restrict__ bo =
        out + (size_t)bc * (Hdim * Wdim) + (ys - 4) * Wdim + x0;

    const bool okL = (cg > 0);
    const bool okR = (cg < NCG - 1);
    const float NI = -CUDART_INF_F;

    float acc[5][4];
    #pragma unroll
    for (int s = 0; s < 5; s++)
        #pragma unroll
        for (int t = 0; t < 4; t++) acc[s][t] = NI;

    // Head: r = 0..4 (gy = ys-2 .. ys+2). Row check needed only for strip 0.
    STEP(0, 0, (ys >= 2), false)
    STEP(1, 1, (ys >= 1), false)
    STEP(2, 2, true,      false)
    STEP(3, 3, true,      false)
    STEP(4, 4, true,      true)

    // Main: r = 5..29, gy in [ys+3, ys+27] subset of [3,223] for every strip:
    // no bounds checks, store every step.
    #pragma unroll 1
    for (int rb = 5; rb < 30; rb += 5) {
        STEP(0, rb + 0, true, true)
        STEP(1, rb + 1, true, true)
        STEP(2, rb + 2, true, true)
        STEP(3, rb + 3, true, true)
        STEP(4, rb + 4, true, true)
    }

    // Tail: r = 30,31 (gy = ys+28, ys+29). Row check only for strip 7.
    STEP(0, 30, (ys + 28 < Hdim), true)
    STEP(1, 31, (ys + 29 < Hdim), true)
}

extern "C" void kernel_launch(void* const* d_in, const int* in_sizes, int n_in,
                              void* d_out, int out_size) {
    const float* x = (const float*)d_in[0];
    float* out = (float*)d_out;

    // Stage weights into constant memory (D2D async copy, graph-capturable).
    cudaMemcpyToSymbolAsync(cw, d_in[1], 32 * 25 * sizeof(float), 0,
                            cudaMemcpyDeviceToDevice, 0);

    dim3 block(NCG, 4, 1);          // 224 threads, one bc per block
    dim3 grid(1, 2, 8 * 32);        // 2 strip-quads, 256 bc images
    tropical_conv_kernel<<<grid, block>>>(x, out);
}